// round 14
// baseline (speedup 1.0000x reference)
#include <cuda_runtime.h>
#include <cuda_fp16.h>
#include <math.h>
#include <stdint.h>

#define BB 256
#define NN 256
#define DD 136
#define HH 128
#define ROWS (BB*NN)

#define K1PAD 152
#define K2PAD 136
#define TM    64
#define NT    256
#define GRID  296
#define NTILES (ROWS / TM)   // 1024
#define NLAM  (8 * BB)       // 2048 lambda units (32 rows x full j each)

// ---------------- scratch globals ----------------
__device__ __align__(16) float4 g_elg[ROWS];        // {exp(s), 1+log2(1+s), 2^label, 0}
__device__ __align__(16) __half g_W1t[HH * K1PAD];
__device__ __align__(16) __half g_W2t[HH * K2PAD];
__device__ unsigned long long g_bar = 0ULL;         // monotonic grid barrier
__device__ unsigned int g_bcnt[BB];                 // monotonic per-batch tile counters

// ---------------- smem layout ----------------
#define A_BYTES  (TM * K1PAD * 2)           // 19456
#define W1_BYTES (128 * K1PAD * 2)
#define W2_BYTES (128 * K2PAD * 2)
#define OFF_A    0
#define OFF_W1   (A_BYTES)
#define OFF_W2   (OFF_W1 + W1_BYTES)
#define OFF_B1   (OFF_W2 + W2_BYTES)        // 93184
#define OFF_B2   (OFF_B1 + 512)
#define OFF_W3   (OFF_B2 + 512)
#define OFF_RED  (OFF_W3 + 512)
#define OFF_EP   (OFF_RED + 512)
#define SMEM_BYTES (OFF_EP + 16)            // 95248 (x2 CTAs < 227KB)

__device__ __forceinline__ uint32_t smem_u32(const void* p) {
    uint32_t a;
    asm("{ .reg .u64 t; cvta.to.shared.u64 t, %1; cvt.u32.u64 %0, t; }" : "=r"(a) : "l"(p));
    return a;
}
__device__ __forceinline__ void cp_async16(uint32_t dst, const void* src) {
    asm volatile("cp.async.cg.shared.global [%0], [%1], 16;" :: "r"(dst), "l"(src));
}
#define CP_COMMIT() asm volatile("cp.async.commit_group;" ::: "memory")
#define CP_WAIT0()  asm volatile("cp.async.wait_group 0;" ::: "memory")

__device__ __forceinline__ void ldsm_x4(uint32_t* r, uint32_t addr) {
    asm volatile("ldmatrix.sync.aligned.m8n8.x4.shared.b16 {%0,%1,%2,%3}, [%4];"
        : "=r"(r[0]), "=r"(r[1]), "=r"(r[2]), "=r"(r[3]) : "r"(addr));
}
__device__ __forceinline__ void mma16816(float* d, const uint32_t* a, uint32_t b0, uint32_t b1) {
    asm volatile("mma.sync.aligned.m16n8k16.row.col.f32.f16.f16.f32 "
        "{%0,%1,%2,%3}, {%4,%5,%6,%7}, {%8,%9}, {%0,%1,%2,%3};"
        : "+f"(d[0]), "+f"(d[1]), "+f"(d[2]), "+f"(d[3])
        : "r"(a[0]), "r"(a[1]), "r"(a[2]), "r"(a[3]), "r"(b0), "r"(b1));
}
__device__ __forceinline__ uint32_t pack_h2(float x, float y) {
    __half h0 = __float2half_rn(x), h1 = __float2half_rn(y);
    return ((uint32_t)__half_as_ushort(h1) << 16) | __half_as_ushort(h0);
}

// ---------------- lambda unit: batch b octant io (32 i x 256 j) ----------------
__device__ __forceinline__ void do_lambda(int u, unsigned int epoch, char* smem,
                                          float* __restrict__ out, int tid)
{
    const int b  = u >> 3;
    const int io = u & 7;

    if (tid == 0) {
        const unsigned int target = 4u * epoch;
        unsigned int v;
        do {
            asm volatile("ld.acquire.gpu.global.u32 %0, [%1];" : "=r"(v) : "l"(&g_bcnt[b]));
        } while (v < target);
    }
    __syncthreads();

    float4* elg  = (float4*)(smem + OFF_A);
    float*  part = (float*)(smem + OFF_A + 4096);
    elg[tid] = g_elg[b * NN + tid];
    __syncthreads();

    const int il = tid & 31;
    const int jh = tid >> 5;
    const int i  = io * 32 + il;
    const float4 me = elg[i];
    const float ei = me.x, Mi = me.y, gi = me.z;

    float acc0 = 0.f, acc1 = 0.f;
    const int j0 = jh * 32;
    #pragma unroll 4
    for (int j = 0; j < 32; j += 2) {
        float4 va = elg[j0 + j];
        float4 vb = elg[j0 + j + 1];
        float sga = gi - va.z;
        float sgb = gi - vb.z;
        float ta = (sga > 0.f) ? ei : va.x;
        float tb = (sgb > 0.f) ? ei : vb.x;
        acc0 += __fdividef(sga * ta, fabsf(fmaxf(Mi, va.y)) * (ei + va.x));
        acc1 += __fdividef(sgb * tb, fabsf(fmaxf(Mi, vb.y)) * (ei + vb.x));
    }
    part[tid] = acc0 + acc1;
    __syncthreads();
    if (tid < 32) {
        float s = 0.f;
        #pragma unroll
        for (int k = 0; k < 8; k++) s += part[tid + 32 * k];
        out[b * NN + io * 32 + tid] = 0.5f * s;
    }
    __syncthreads();   // smem free before reuse
}

// ---------------- persistent fused MLP + lambda ----------------
__global__ __launch_bounds__(NT, 2)
void fused_persist(const float* __restrict__ feat, const int* __restrict__ labels,
                   const float* __restrict__ W1, const float* __restrict__ b1,
                   const float* __restrict__ W2, const float* __restrict__ b2,
                   const float* __restrict__ W3, const float* __restrict__ b3,
                   float* __restrict__ out)
{
    extern __shared__ char smem[];
    __half* A  = (__half*)(smem + OFF_A);
    float* sB1 = (float*)(smem + OFF_B1);
    float* sB2 = (float*)(smem + OFF_B2);
    float* sW3 = (float*)(smem + OFF_W3);
    float* red = (float*)(smem + OFF_RED);
    unsigned int* sEp = (unsigned int*)(smem + OFF_EP);

    const int tid  = threadIdx.x;
    const int lane = tid & 31;
    const int wid  = tid >> 5;
    const int m0    = (wid >> 1) * 16;
    const int nside = (wid & 1) * 64;

    const uint32_t uA  = smem_u32(smem + OFF_A);
    const uint32_t uW1 = smem_u32(smem + OFF_W1);
    const uint32_t uW2 = smem_u32(smem + OFF_W2);

    const int a_row = m0 + (lane & 7) + ((lane >> 3) & 1) * 8;
    const int a_kof = (lane >> 4) * 8;
    const int w_rof = (lane & 7) + (lane >> 4) * 8;
    const int w_kof = ((lane >> 3) & 1) * 8;

    // ===== phase 0: weight prep (grid-strided), then global barrier =====
    for (int idx = blockIdx.x * NT + tid; idx < 152 * 32 + 128 * 32; idx += GRID * NT) {
        if (idx < 152 * 32) {
            int k = idx >> 5, nq = (idx & 31) * 4;
            float4 v = (k < DD) ? *(const float4*)(W1 + k * HH + nq)
                                : make_float4(0.f, 0.f, 0.f, 0.f);
            g_W1t[(nq + 0) * K1PAD + k] = __float2half_rn(v.x);
            g_W1t[(nq + 1) * K1PAD + k] = __float2half_rn(v.y);
            g_W1t[(nq + 2) * K1PAD + k] = __float2half_rn(v.z);
            g_W1t[(nq + 3) * K1PAD + k] = __float2half_rn(v.w);
        } else {
            int idx2 = idx - 152 * 32;
            int k = idx2 >> 5, nq = (idx2 & 31) * 4;
            float4 v = *(const float4*)(W2 + k * HH + nq);
            g_W2t[(nq + 0) * K2PAD + k] = __float2half_rn(v.x);
            g_W2t[(nq + 1) * K2PAD + k] = __float2half_rn(v.y);
            g_W2t[(nq + 2) * K2PAD + k] = __float2half_rn(v.z);
            g_W2t[(nq + 3) * K2PAD + k] = __float2half_rn(v.w);
        }
    }
    __threadfence();
    __syncthreads();
    if (tid == 0) {
        unsigned long long old = atomicAdd(&g_bar, 1ULL);
        unsigned long long target = (old / GRID + 1ULL) * GRID;
        sEp[0] = (unsigned int)(old / GRID) + 1u;     // epoch (same for all CTAs this replay)
        unsigned long long v;
        do {
            asm volatile("ld.acquire.gpu.global.u64 %0, [%1];" : "=l"(v) : "l"(&g_bar));
        } while (v < target);
    }
    __syncthreads();
    const unsigned int epoch = sEp[0];

    // ===== stage weights to smem ONCE =====
    {
        const char* s;
        s = (const char*)g_W1t;
        for (int i = tid; i < W1_BYTES / 16; i += NT) cp_async16(uW1 + i * 16, s + i * 16);
        s = (const char*)g_W2t;
        for (int i = tid; i < W2_BYTES / 16; i += NT) cp_async16(uW2 + i * 16, s + i * 16);
        CP_COMMIT();
    }
    if (tid < 128) { sB1[tid] = b1[tid]; sB2[tid] = b2[tid]; sW3[tid] = W3[tid]; }
    const float b3v = __ldg(b3);
    CP_WAIT0();
    __syncthreads();

    // ===== interleaved tile rounds + lambda units =====
    const int r  = tid >> 2;
    const int c4 = tid & 3;
    float2 v[17];
    {   // initial prefetch
        const float* fb = feat + ((long)blockIdx.x * TM + r) * DD + 2 * c4;
        #pragma unroll
        for (int it = 0; it < 17; it++) v[it] = *(const float2*)(fb + 8 * it);
    }

    int lam_u = blockIdx.x;

    #pragma unroll 1
    for (int round = 0; round < 4; round++) {
        const int tile = blockIdx.x + round * GRID;
        if (tile < NTILES) {
            const long row0 = (long)tile * TM;

            // ---- store prefetched features -> fp16 A ----
            #pragma unroll
            for (int it = 0; it < 17; it++) {
                const int p = c4 + 4 * it;
                *(uint32_t*)(A + r * K1PAD + 2 * p) = pack_h2(v[it].x, v[it].y);
            }
            *(uint32_t*)(A + r * K1PAD + 2 * (68 + c4)) = 0;
            *(uint32_t*)(A + r * K1PAD + 2 * (72 + c4)) = 0;
            __syncthreads();

            // ---- prefetch next round's features ----
            {
                const int nxt = tile + GRID;
                if (nxt < NTILES) {
                    const float* fb = feat + ((long)nxt * TM + r) * DD + 2 * c4;
                    #pragma unroll
                    for (int it = 0; it < 17; it++) v[it] = *(const float2*)(fb + 8 * it);
                }
            }

            float acc[8][4];
            #pragma unroll
            for (int t = 0; t < 8; t++)
                #pragma unroll
                for (int q = 0; q < 4; q++) acc[t][q] = 0.f;

            // ---- layer 1: 9 ksteps ----
            #pragma unroll
            for (int ks = 0; ks < 9; ks++) {
                const int k0 = ks * 16;
                uint32_t a[4];
                ldsm_x4(a, uA + (a_row * K1PAD + k0 + a_kof) * 2);
                #pragma unroll
                for (int np = 0; np < 4; np++) {
                    const int n0 = nside + np * 16;
                    uint32_t w[4];
                    ldsm_x4(w, uW1 + ((n0 + w_rof) * K1PAD + k0 + w_kof) * 2);
                    mma16816(acc[2*np],   a, w[0], w[1]);
                    mma16816(acc[2*np+1], a, w[2], w[3]);
                }
            }
            __syncthreads();

            // ---- epilogue 1 ----
            {
                const int rA = m0 + (lane >> 2);
                #pragma unroll
                for (int nt = 0; nt < 8; nt++) {
                    const int c = nside + nt * 8 + (lane & 3) * 2;
                    float v0 = fmaxf(acc[nt][0] + sB1[c],     0.f);
                    float v1 = fmaxf(acc[nt][1] + sB1[c + 1], 0.f);
                    float v2 = fmaxf(acc[nt][2] + sB1[c],     0.f);
                    float v3 = fmaxf(acc[nt][3] + sB1[c + 1], 0.f);
                    *(uint32_t*)(A + rA * K2PAD + c)       = pack_h2(v0, v1);
                    *(uint32_t*)(A + (rA + 8) * K2PAD + c) = pack_h2(v2, v3);
                }
            }
            __syncthreads();

            #pragma unroll
            for (int t = 0; t < 8; t++)
                #pragma unroll
                for (int q = 0; q < 4; q++) acc[t][q] = 0.f;

            // ---- layer 2: 8 ksteps ----
            #pragma unroll
            for (int ks = 0; ks < 8; ks++) {
                const int k0 = ks * 16;
                uint32_t a[4];
                ldsm_x4(a, uA + (a_row * K2PAD + k0 + a_kof) * 2);
                #pragma unroll
                for (int np = 0; np < 4; np++) {
                    const int n0 = nside + np * 16;
                    uint32_t w[4];
                    ldsm_x4(w, uW2 + ((n0 + w_rof) * K2PAD + k0 + w_kof) * 2);
                    mma16816(acc[2*np],   a, w[0], w[1]);
                    mma16816(acc[2*np+1], a, w[2], w[3]);
                }
            }

            // ---- epilogue 2: scores -> g_elg, then release counter ----
            {
                float pl = 0.f, ph = 0.f;
                #pragma unroll
                for (int nt = 0; nt < 8; nt++) {
                    const int c = nside + nt * 8 + (lane & 3) * 2;
                    pl = fmaf(fmaxf(acc[nt][0] + sB2[c],     0.f), sW3[c],     pl);
                    pl = fmaf(fmaxf(acc[nt][1] + sB2[c + 1], 0.f), sW3[c + 1], pl);
                    ph = fmaf(fmaxf(acc[nt][2] + sB2[c],     0.f), sW3[c],     ph);
                    ph = fmaf(fmaxf(acc[nt][3] + sB2[c + 1], 0.f), sW3[c + 1], ph);
                }
                pl += __shfl_xor_sync(0xFFFFFFFF, pl, 1);
                pl += __shfl_xor_sync(0xFFFFFFFF, pl, 2);
                ph += __shfl_xor_sync(0xFFFFFFFF, ph, 1);
                ph += __shfl_xor_sync(0xFFFFFFFF, ph, 2);
                if ((lane & 3) == 0) {
                    const int rr = m0 + (lane >> 2);
                    red[rr * 2 + (wid & 1)]       = pl;
                    red[(rr + 8) * 2 + (wid & 1)] = ph;
                }
            }
            __syncthreads();
            if (tid < TM) {
                float s = red[tid * 2] + red[tid * 2 + 1] + b3v;
                int   l = labels[row0 + tid];
                float e = __expf(s);
                float M = 1.0f + __log2f(1.0f + s);
                float g = __int_as_float((l + 127) << 23);   // 2^l
                g_elg[row0 + tid] = make_float4(e, M, g, 0.f);
            }
            __syncthreads();
            if (tid == 0) {
                __threadfence();
                atomicAdd(&g_bcnt[tile >> 2], 1u);
            }
        }

        // ---- interleave: 2 lambda units per round (batches from prior rounds) ----
        if (round >= 1) {
            #pragma unroll 1
            for (int q = 0; q < 2; q++) {
                if (lam_u < NLAM) {
                    do_lambda(lam_u, epoch, smem, out, tid);
                    lam_u += GRID;
                }
            }
        }
    }

    // ---- drain remaining lambda units ----
    #pragma unroll 1
    while (lam_u < NLAM) {
        do_lambda(lam_u, epoch, smem, out, tid);
        lam_u += GRID;
    }
}

extern "C" void kernel_launch(void* const* d_in, const int* in_sizes, int n_in,
                              void* d_out, int out_size)
{
    const float* feat   = (const float*)d_in[0];
    const int*   labels = (const int*)d_in[1];
    const float* W1 = (const float*)d_in[2];
    const float* b1 = (const float*)d_in[3];
    const float* W2 = (const float*)d_in[4];
    const float* b2 = (const float*)d_in[5];
    const float* W3 = (const float*)d_in[6];
    const float* b3 = (const float*)d_in[7];
    float* out = (float*)d_out;

    static bool attr_set = false;
    if (!attr_set) {
        cudaFuncSetAttribute(fused_persist, cudaFuncAttributeMaxDynamicSharedMemorySize,
                             (int)SMEM_BYTES);
        attr_set = true;
    }

    fused_persist<<<GRID, NT, SMEM_BYTES>>>(feat, labels, W1, b1, W2, b2, W3, b3, out);
}